// round 11
// baseline (speedup 1.0000x reference)
#include <cuda_runtime.h>
#include <cuda_bf16.h>
#include <cstdint>

#define NT    32768      // B*S = 64*512
#define HID   768
#define INTER 3072

// ---------------- static device scratch (allocation-free rule) ----------------
__device__ float         g_base[(size_t)NT * HID];     // base embedding; GEMM2 adds into it
__device__ __nv_bfloat16 g_Ah[(size_t)NT * HID];       // compacted fps rows, bf16 hi
__device__ __nv_bfloat16 g_Al[(size_t)NT * HID];       // bf16 lo
__device__ __nv_bfloat16 g_C1h[(size_t)NT * INTER];    // GEMM1 relu output, split
__device__ __nv_bfloat16 g_C1l[(size_t)NT * INTER];
__device__ __nv_bfloat16 g_fc1h[(size_t)HID * INTER];  // weights, transposed [N][K], split
__device__ __nv_bfloat16 g_fc1l[(size_t)HID * INTER];
__device__ __nv_bfloat16 g_fc2h[(size_t)INTER * HID];
__device__ __nv_bfloat16 g_fc2l[(size_t)INTER * HID];
__device__ int g_rows[NT];
__device__ int g_count;

// ---------------- helpers ----------------
__device__ __forceinline__ void split2(float a, float b, __nv_bfloat162& h, __nv_bfloat162& l) {
    __nv_bfloat16 ah = __float2bfloat16_rn(a);
    __nv_bfloat16 bh = __float2bfloat16_rn(b);
    h.x = ah; h.y = bh;
    l.x = __float2bfloat16_rn(a - __bfloat162float(ah));
    l.y = __float2bfloat16_rn(b - __bfloat162float(bh));
}
__device__ __forceinline__ void cp16(void* s, const void* g) {
    uint32_t a = (uint32_t)__cvta_generic_to_shared(s);
    asm volatile("cp.async.cg.shared.global [%0], [%1], 16;\n" :: "r"(a), "l"(g));
}
__device__ __forceinline__ uint32_t ld32(const __nv_bfloat16* p) {
    return *(const uint32_t*)p;
}
__device__ __forceinline__ void mma16(float* d, const uint32_t* a, const uint32_t* b) {
    asm volatile(
        "mma.sync.aligned.m16n8k16.row.col.f32.bf16.bf16.f32 "
        "{%0,%1,%2,%3}, {%4,%5,%6,%7}, {%8,%9}, {%0,%1,%2,%3};\n"
        : "+f"(d[0]), "+f"(d[1]), "+f"(d[2]), "+f"(d[3])
        : "r"(a[0]), "r"(a[1]), "r"(a[2]), "r"(a[3]), "r"(b[0]), "r"(b[1]));
}

// ---------------- K0: zero counter ----------------
__global__ void zero_kernel() { g_count = 0; }

// ---------------- Kw: transpose + bf16-split weights: w[K][N] -> oh/ol[N][K] ----------------
template <int WHICH>
__global__ void __launch_bounds__(256) transpose_split(const float* __restrict__ w, int K, int N)
{
    __nv_bfloat16* __restrict__ oh = (WHICH == 1) ? g_fc1h : g_fc2h;
    __nv_bfloat16* __restrict__ ol = (WHICH == 1) ? g_fc1l : g_fc2l;
    __shared__ float tile[32][33];
    int bk = blockIdx.x * 32, bn = blockIdx.y * 32;
    int tx = threadIdx.x, ty = threadIdx.y;            // 32 x 8
#pragma unroll
    for (int i = 0; i < 4; i++)
        tile[ty + i * 8][tx] = w[(size_t)(bk + ty + i * 8) * N + bn + tx];
    __syncthreads();
#pragma unroll
    for (int i = 0; i < 4; i++) {
        int n = bn + ty + i * 8, k = bk + tx;
        float v = tile[tx][ty + i * 8];
        __nv_bfloat16 h = __float2bfloat16_rn(v);
        oh[(size_t)n * K + k] = h;
        ol[(size_t)n * K + k] = __float2bfloat16_rn(v - __bfloat162float(h));
    }
}

// ---------------- K1: base embedding + SMILES compaction (warp per token) ----------------
__global__ void __launch_bounds__(256) base_kernel(
    const float* __restrict__ fps, const int* __restrict__ words,
    const float* __restrict__ vals, const int* __restrict__ tts,
    const int* __restrict__ poss,
    const float* __restrict__ prop_emb, const float* __restrict__ val_w,
    const float* __restrict__ val_b, const float* __restrict__ pos_emb,
    const float* __restrict__ type_emb)
{
    int widx = (blockIdx.x * blockDim.x + threadIdx.x) >> 5;
    int lane = threadIdx.x & 31;
    if (widx >= NT) return;
    int t  = widx;
    int tt = tts[t];
    int p  = poss[t];

    const float4* pe = (const float4*)(pos_emb  + (size_t)p  * HID);
    const float4* te = (const float4*)(type_emb + (size_t)tt * HID);
    float4 o[6];
#pragma unroll
    for (int i = 0; i < 6; i++) {
        int j = lane + i * 32;
        float4 a = pe[j], b = te[j];
        o[i] = make_float4(a.x + b.x, a.y + b.y, a.z + b.z, a.w + b.w);
    }
    if (tt == 0) {
        int w = words[t];
        const float4* we = (const float4*)(prop_emb + (size_t)w * HID);
#pragma unroll
        for (int i = 0; i < 6; i++) {
            float4 a = we[lane + i * 32];
            o[i].x += a.x; o[i].y += a.y; o[i].z += a.z; o[i].w += a.w;
        }
    } else if (tt == 2) {
        float v = vals[t];
        const float4* vw = (const float4*)val_w;
        const float4* vb = (const float4*)val_b;
#pragma unroll
        for (int i = 0; i < 6; i++) {
            int j = lane + i * 32;
            float4 a = vw[j], b = vb[j];
            o[i].x += v * a.x + b.x; o[i].y += v * a.y + b.y;
            o[i].z += v * a.z + b.z; o[i].w += v * a.w + b.w;
        }
    }
    float4* dst = (float4*)(g_base + (size_t)t * HID);
#pragma unroll
    for (int i = 0; i < 6; i++) dst[lane + i * 32] = o[i];

    if (tt == 1) {
        int slot = 0;
        if (lane == 0) slot = atomicAdd(&g_count, 1);
        slot = __shfl_sync(0xffffffffu, slot, 0);
        if (lane == 0) g_rows[slot] = t;
        const float4* src = (const float4*)(fps + (size_t)t * HID);
        __nv_bfloat162* dh = (__nv_bfloat162*)(g_Ah + (size_t)slot * HID);
        __nv_bfloat162* dl = (__nv_bfloat162*)(g_Al + (size_t)slot * HID);
#pragma unroll
        for (int i = 0; i < 6; i++) {
            int j = lane + i * 32;
            float4 x = src[j];
            __nv_bfloat162 h0, l0, h1, l1;
            split2(x.x, x.y, h0, l0);
            split2(x.z, x.w, h1, l1);
            dh[2 * j]     = h0;  dh[2 * j + 1] = h1;
            dl[2 * j]     = l0;  dl[2 * j + 1] = l1;
        }
    }
}

// ---------------- BF16x3 tensor-core GEMM, 128x128x32 CTA tile ----------------
// EPI==1: C1 = relu(A @ fc1 + b1), stored bf16-split (compacted rows)
// EPI==2: g_base[rows[m]] += A(C1) @ fc2 + b2 (fp32 scatter-add)
#define BM  128
#define BN  128
#define BK  32
#define TS  40                         // smem row stride, bf16 elems (80 B; conflict-free, 16B-mult)
#define TILE_E (128 * TS)              // 5120 bf16 per tile
#define STAGE_E (4 * TILE_E)           // Ah, Al, Bh, Bl
#define SMEM_E (2 * STAGE_E)           // 40960 bf16 = 81920 B

template <int EPI>
__global__ void __launch_bounds__(256, 2) gemm_bf16x3(const float* __restrict__ bias)
{
    constexpr int KD = (EPI == 1) ? HID   : INTER;     // k extent (A row stride, B row stride)
    constexpr int ND = (EPI == 1) ? INTER : HID;       // n extent (C row stride)
    const __nv_bfloat16* __restrict__ Ah = (EPI == 1) ? g_Ah  : g_C1h;
    const __nv_bfloat16* __restrict__ Al = (EPI == 1) ? g_Al  : g_C1l;
    const __nv_bfloat16* __restrict__ Bh = (EPI == 1) ? g_fc1h : g_fc2h;
    const __nv_bfloat16* __restrict__ Bl = (EPI == 1) ? g_fc1l : g_fc2l;

    int count = __ldg(&g_count);
    int bm = blockIdx.y, bn = blockIdx.x;
    if (bm * BM >= count) return;

    extern __shared__ __nv_bfloat16 smem[];
    int tid  = threadIdx.x;
    int warp = tid >> 5, lane = tid & 31;
    int wm = warp >> 1, wn = warp & 1;                 // 4x2 warp grid
    int m0 = wm * 32, n0 = wn * 64;                    // warp tile 32x64
    int g  = lane >> 2, t4 = lane & 3;

    const int KT = KD / BK;

    // loader: per stage, 4 tiles x 512 16B-chunks; 8 cp.async per thread
    auto load_tiles = [&](int stage, int k0) {
        __nv_bfloat16* sAh = smem + stage * STAGE_E;
        __nv_bfloat16* sAl = sAh + TILE_E;
        __nv_bfloat16* sBh = sAl + TILE_E;
        __nv_bfloat16* sBl = sBh + TILE_E;
#pragma unroll
        for (int i = 0; i < 2; i++) {
            int c = i * 256 + tid;
            int r = c >> 2, c4 = c & 3;                 // row, 8-elem chunk in row
            size_t goffA = (size_t)(bm * BM + r) * KD + k0 + c4 * 8;
            size_t goffB = (size_t)(bn * BN + r) * KD + k0 + c4 * 8;
            cp16(sAh + r * TS + c4 * 8, Ah + goffA);
            cp16(sAl + r * TS + c4 * 8, Al + goffA);
            cp16(sBh + r * TS + c4 * 8, Bh + goffB);
            cp16(sBl + r * TS + c4 * 8, Bl + goffB);
        }
    };

    load_tiles(0, 0);
    asm volatile("cp.async.commit_group;\n");

    float acc[2][8][4];
#pragma unroll
    for (int mi = 0; mi < 2; mi++)
#pragma unroll
        for (int ni = 0; ni < 8; ni++)
#pragma unroll
            for (int q = 0; q < 4; q++) acc[mi][ni][q] = 0.f;

    for (int kt = 0; kt < KT; ++kt) {
        if (kt + 1 < KT) {
            load_tiles((kt + 1) & 1, (kt + 1) * BK);
            asm volatile("cp.async.commit_group;\n");
            asm volatile("cp.async.wait_group 1;\n");
        } else {
            asm volatile("cp.async.wait_group 0;\n");
        }
        __syncthreads();

        const __nv_bfloat16* sAh = smem + (kt & 1) * STAGE_E;
        const __nv_bfloat16* sAl = sAh + TILE_E;
        const __nv_bfloat16* sBh = sAl + TILE_E;
        const __nv_bfloat16* sBl = sBh + TILE_E;

#pragma unroll
        for (int ks = 0; ks < 2; ks++) {
            int k = ks * 16;
            uint32_t ah[2][4], al[2][4];
#pragma unroll
            for (int mi = 0; mi < 2; mi++) {
                int r0 = m0 + mi * 16 + g;
                ah[mi][0] = ld32(sAh + (r0)     * TS + k + 2 * t4);
                ah[mi][1] = ld32(sAh + (r0 + 8) * TS + k + 2 * t4);
                ah[mi][2] = ld32(sAh + (r0)     * TS + k + 8 + 2 * t4);
                ah[mi][3] = ld32(sAh + (r0 + 8) * TS + k + 8 + 2 * t4);
                al[mi][0] = ld32(sAl + (r0)     * TS + k + 2 * t4);
                al[mi][1] = ld32(sAl + (r0 + 8) * TS + k + 2 * t4);
                al[mi][2] = ld32(sAl + (r0)     * TS + k + 8 + 2 * t4);
                al[mi][3] = ld32(sAl + (r0 + 8) * TS + k + 8 + 2 * t4);
            }
#pragma unroll
            for (int ni = 0; ni < 8; ni++) {
                int c0 = n0 + ni * 8 + g;
                uint32_t bh[2], bl[2];
                bh[0] = ld32(sBh + (size_t)c0 * TS + k + 2 * t4);
                bh[1] = ld32(sBh + (size_t)c0 * TS + k + 8 + 2 * t4);
                bl[0] = ld32(sBl + (size_t)c0 * TS + k + 2 * t4);
                bl[1] = ld32(sBl + (size_t)c0 * TS + k + 8 + 2 * t4);
#pragma unroll
                for (int mi = 0; mi < 2; mi++) {
                    mma16(acc[mi][ni], ah[mi], bh);    // hi*hi
                    mma16(acc[mi][ni], ah[mi], bl);    // hi*lo
                    mma16(acc[mi][ni], al[mi], bh);    // lo*hi
                }
            }
        }
        __syncthreads();
    }

    // epilogue
#pragma unroll
    for (int mi = 0; mi < 2; mi++) {
#pragma unroll
        for (int half = 0; half < 2; half++) {
            int r  = m0 + mi * 16 + half * 8 + g;
            int gm = bm * BM + r;
            if (gm < count) {
                if (EPI == 1) {
                    size_t rowoff = (size_t)gm * ND;
#pragma unroll
                    for (int ni = 0; ni < 8; ni++) {
                        int cc = bn * BN + n0 + ni * 8 + 2 * t4;
                        float2 bb = *(const float2*)(bias + cc);
                        float v0 = acc[mi][ni][half * 2 + 0] + bb.x;
                        float v1 = acc[mi][ni][half * 2 + 1] + bb.y;
                        v0 = v0 > 0.f ? v0 : 0.f;
                        v1 = v1 > 0.f ? v1 : 0.f;
                        __nv_bfloat162 h, l;
                        split2(v0, v1, h, l);
                        *(__nv_bfloat162*)(g_C1h + rowoff + cc) = h;
                        *(__nv_bfloat162*)(g_C1l + rowoff + cc) = l;
                    }
                } else {
                    int orow = g_rows[gm];
                    size_t rowoff = (size_t)orow * ND;
#pragma unroll
                    for (int ni = 0; ni < 8; ni++) {
                        int cc = bn * BN + n0 + ni * 8 + 2 * t4;
                        float2 bb  = *(const float2*)(bias + cc);
                        float2* p  = (float2*)(g_base + rowoff + cc);
                        float2 old = *p;
                        old.x += acc[mi][ni][half * 2 + 0] + bb.x;
                        old.y += acc[mi][ni][half * 2 + 1] + bb.y;
                        *p = old;
                    }
                }
            }
        }
    }
}

// ---------------- K4: LayerNorm (warp per row) ----------------
__global__ void __launch_bounds__(256) ln_kernel(const float* __restrict__ gam,
                                                 const float* __restrict__ bet,
                                                 float* __restrict__ out)
{
    int widx = (blockIdx.x * blockDim.x + threadIdx.x) >> 5;
    int lane = threadIdx.x & 31;
    if (widx >= NT) return;

    const float4* src = (const float4*)(g_base + (size_t)widx * HID);
    float4 v[6];
    float s = 0.f, s2 = 0.f;
#pragma unroll
    for (int i = 0; i < 6; i++) {
        v[i] = src[lane + i * 32];
        s  += v[i].x + v[i].y + v[i].z + v[i].w;
        s2 += v[i].x * v[i].x + v[i].y * v[i].y + v[i].z * v[i].z + v[i].w * v[i].w;
    }
#pragma unroll
    for (int o = 16; o > 0; o >>= 1) {
        s  += __shfl_xor_sync(0xffffffffu, s,  o);
        s2 += __shfl_xor_sync(0xffffffffu, s2, o);
    }
    float mu  = s * (1.f / HID);
    float var = s2 * (1.f / HID) - mu * mu;
    float inv = rsqrtf(var + 1e-12f);

    const float4* gg = (const float4*)gam;
    const float4* bb = (const float4*)bet;
    float4* dst = (float4*)(out + (size_t)widx * HID);
#pragma unroll
    for (int i = 0; i < 6; i++) {
        int j = lane + i * 32;
        float4 G = gg[j], Bv = bb[j];
        float4 o;
        o.x = (v[i].x - mu) * inv * G.x + Bv.x;
        o.y = (v[i].y - mu) * inv * G.y + Bv.y;
        o.z = (v[i].z - mu) * inv * G.z + Bv.z;
        o.w = (v[i].w - mu) * inv * G.w + Bv.w;
        dst[j] = o;
    }
}

// ---------------- launch ----------------
extern "C" void kernel_launch(void* const* d_in, const int* in_sizes, int n_in,
                              void* d_out, int out_size)
{
    // Locate SMILES_fps by its unique size (B*S*FP_DIM = 25,165,824); any scalar
    // inputs (batch_size, max_batch_seq_len) precede it. Rest follow in order.
    int off = 0;
    for (int i = 0; i < n_in; i++)
        if (in_sizes[i] == NT * HID) { off = i; break; }

    const float* fps   = (const float*)d_in[off + 0];
    const int*   words = (const int*)  d_in[off + 1];
    const float* vals  = (const float*)d_in[off + 2];
    const int*   tts   = (const int*)  d_in[off + 3];
    const int*   poss  = (const int*)  d_in[off + 4];
    const float* fc1w  = (const float*)d_in[off + 5];
    const float* fc1b  = (const float*)d_in[off + 6];
    const float* fc2w  = (const float*)d_in[off + 7];
    const float* fc2b  = (const float*)d_in[off + 8];
    const float* prop  = (const float*)d_in[off + 9];
    const float* valw  = (const float*)d_in[off + 10];
    const float* valb  = (const float*)d_in[off + 11];
    const float* pose  = (const float*)d_in[off + 12];
    const float* typee = (const float*)d_in[off + 13];
    const float* lng   = (const float*)d_in[off + 14];
    const float* lnb   = (const float*)d_in[off + 15];
    float* out = (float*)d_out;

    const int smem_bytes = SMEM_E * 2;      // 81920
    cudaFuncSetAttribute(gemm_bf16x3<1>, cudaFuncAttributeMaxDynamicSharedMemorySize, smem_bytes);
    cudaFuncSetAttribute(gemm_bf16x3<2>, cudaFuncAttributeMaxDynamicSharedMemorySize, smem_bytes);

    zero_kernel<<<1, 1>>>();
    transpose_split<1><<<dim3(HID / 32, INTER / 32), dim3(32, 8)>>>(fc1w, HID, INTER);
    transpose_split<2><<<dim3(INTER / 32, HID / 32), dim3(32, 8)>>>(fc2w, INTER, HID);
    base_kernel<<<NT / 8, 256>>>(fps, words, vals, tts, poss, prop, valw, valb, pose, typee);
    gemm_bf16x3<1><<<dim3(INTER / BN, NT / BM), 256, smem_bytes>>>(fc1b);
    gemm_bf16x3<2><<<dim3(HID / BN, NT / BM), 256, smem_bytes>>>(fc2b);
    ln_kernel<<<NT / 8, 256>>>(lng, lnb, out);
}

// round 17
// speedup vs baseline: 1.3813x; 1.3813x over previous
#include <cuda_runtime.h>
#include <cuda_fp16.h>
#include <cstdint>

#define NT    32768      // B*S = 64*512
#define HID   768
#define INTER 3072

// ---------------- static device scratch (allocation-free rule) ----------------
__device__ float  g_base[(size_t)NT * HID];    // base embedding; GEMM2 adds into it
__device__ __half g_A   [(size_t)NT * HID];    // compacted fps rows, fp16 (single)
__device__ __half g_C1  [(size_t)NT * INTER];  // GEMM1 relu output, fp16 (single)
__device__ __half g_fc1h[(size_t)HID * INTER]; // weights, transposed [N][K], split hi/lo
__device__ __half g_fc1l[(size_t)HID * INTER];
__device__ __half g_fc2h[(size_t)INTER * HID];
__device__ __half g_fc2l[(size_t)INTER * HID];
__device__ int g_rows[NT];
__device__ int g_count;

// ---------------- helpers ----------------
__device__ __forceinline__ void cp16(void* s, const void* g) {
    uint32_t a = (uint32_t)__cvta_generic_to_shared(s);
    asm volatile("cp.async.cg.shared.global [%0], [%1], 16;\n" :: "r"(a), "l"(g));
}
__device__ __forceinline__ uint32_t ld32(const __half* p) {
    return *(const uint32_t*)p;
}
__device__ __forceinline__ void mma16(float* d, const uint32_t* a, const uint32_t* b) {
    asm volatile(
        "mma.sync.aligned.m16n8k16.row.col.f32.f16.f16.f32 "
        "{%0,%1,%2,%3}, {%4,%5,%6,%7}, {%8,%9}, {%0,%1,%2,%3};\n"
        : "+f"(d[0]), "+f"(d[1]), "+f"(d[2]), "+f"(d[3])
        : "r"(a[0]), "r"(a[1]), "r"(a[2]), "r"(a[3]), "r"(b[0]), "r"(b[1]));
}

// ---------------- K0: zero counter ----------------
__global__ void zero_kernel() { g_count = 0; }

// ---------------- Kw: transpose + fp16-split weights: w[K][N] -> oh/ol[N][K] ----------------
template <int WHICH>
__global__ void __launch_bounds__(256) transpose_split(const float* __restrict__ w, int K, int N)
{
    __half* __restrict__ oh = (WHICH == 1) ? g_fc1h : g_fc2h;
    __half* __restrict__ ol = (WHICH == 1) ? g_fc1l : g_fc2l;
    __shared__ float tile[32][33];
    int bk = blockIdx.x * 32, bn = blockIdx.y * 32;
    int tx = threadIdx.x, ty = threadIdx.y;            // 32 x 8
#pragma unroll
    for (int i = 0; i < 4; i++)
        tile[ty + i * 8][tx] = w[(size_t)(bk + ty + i * 8) * N + bn + tx];
    __syncthreads();
#pragma unroll
    for (int i = 0; i < 4; i++) {
        int n = bn + ty + i * 8, k = bk + tx;
        float v = tile[tx][ty + i * 8];
        __half h = __float2half_rn(v);
        oh[(size_t)n * K + k] = h;
        ol[(size_t)n * K + k] = __float2half_rn(v - __half2float(h));
    }
}

// ---------------- K1: base embedding + SMILES compaction (warp per token) ----------------
__global__ void __launch_bounds__(256) base_kernel(
    const float* __restrict__ fps, const int* __restrict__ words,
    const float* __restrict__ vals, const int* __restrict__ tts,
    const int* __restrict__ poss,
    const float* __restrict__ prop_emb, const float* __restrict__ val_w,
    const float* __restrict__ val_b, const float* __restrict__ pos_emb,
    const float* __restrict__ type_emb)
{
    int widx = (blockIdx.x * blockDim.x + threadIdx.x) >> 5;
    int lane = threadIdx.x & 31;
    if (widx >= NT) return;
    int t  = widx;
    int tt = tts[t];
    int p  = poss[t];

    const float4* pe = (const float4*)(pos_emb  + (size_t)p  * HID);
    const float4* te = (const float4*)(type_emb + (size_t)tt * HID);
    float4 o[6];
#pragma unroll
    for (int i = 0; i < 6; i++) {
        int j = lane + i * 32;
        float4 a = pe[j], b = te[j];
        o[i] = make_float4(a.x + b.x, a.y + b.y, a.z + b.z, a.w + b.w);
    }
    if (tt == 0) {
        int w = words[t];
        const float4* we = (const float4*)(prop_emb + (size_t)w * HID);
#pragma unroll
        for (int i = 0; i < 6; i++) {
            float4 a = we[lane + i * 32];
            o[i].x += a.x; o[i].y += a.y; o[i].z += a.z; o[i].w += a.w;
        }
    } else if (tt == 2) {
        float v = vals[t];
        const float4* vw = (const float4*)val_w;
        const float4* vb = (const float4*)val_b;
#pragma unroll
        for (int i = 0; i < 6; i++) {
            int j = lane + i * 32;
            float4 a = vw[j], b = vb[j];
            o[i].x += v * a.x + b.x; o[i].y += v * a.y + b.y;
            o[i].z += v * a.z + b.z; o[i].w += v * a.w + b.w;
        }
    }
    float4* dst = (float4*)(g_base + (size_t)t * HID);
#pragma unroll
    for (int i = 0; i < 6; i++) dst[lane + i * 32] = o[i];

    if (tt == 1) {
        int slot = 0;
        if (lane == 0) slot = atomicAdd(&g_count, 1);
        slot = __shfl_sync(0xffffffffu, slot, 0);
        if (lane == 0) g_rows[slot] = t;
        const float4* src = (const float4*)(fps + (size_t)t * HID);
        __half2* d = (__half2*)(g_A + (size_t)slot * HID);
#pragma unroll
        for (int i = 0; i < 6; i++) {
            int j = lane + i * 32;
            float4 x = src[j];
            d[2 * j]     = __floats2half2_rn(x.x, x.y);
            d[2 * j + 1] = __floats2half2_rn(x.z, x.w);
        }
    }
}

// ---------------- FP16x2 tensor-core GEMM, 128x128x32 CTA tile ----------------
// C ≈ A_h @ (B_h + B_l): A rounded to fp16 once; B split hi/lo. 2 mma passes.
// EPI==1: C1 = relu(A @ fc1 + b1), stored fp16 (compacted rows)
// EPI==2: g_base[rows[m]] += A(C1) @ fc2 + b2 (fp32 scatter-add)
#define BM  128
#define BN  128
#define BK  32
#define TS  40                         // smem row stride, fp16 elems (80 B; conflict-free, 16B-mult)
#define TILE_E (128 * TS)              // 5120 halves per tile
#define STAGE_E (3 * TILE_E)           // A, Bh, Bl
#define SMEM_E (2 * STAGE_E)           // 30720 halves = 61440 B

template <int EPI>
__global__ void __launch_bounds__(256, 2) gemm_fp16x2(const float* __restrict__ bias)
{
    constexpr int KD = (EPI == 1) ? HID   : INTER;     // k extent (A row stride, B row stride)
    constexpr int ND = (EPI == 1) ? INTER : HID;       // n extent (C row stride)
    const __half* __restrict__ Ap = (EPI == 1) ? g_A   : g_C1;
    const __half* __restrict__ Bh = (EPI == 1) ? g_fc1h : g_fc2h;
    const __half* __restrict__ Bl = (EPI == 1) ? g_fc1l : g_fc2l;

    int count = __ldg(&g_count);
    int bm = blockIdx.y, bn = blockIdx.x;
    if (bm * BM >= count) return;

    extern __shared__ __half smem[];
    int tid  = threadIdx.x;
    int warp = tid >> 5, lane = tid & 31;
    int wm = warp >> 1, wn = warp & 1;                 // 4x2 warp grid
    int m0 = wm * 32, n0 = wn * 64;                    // warp tile 32x64
    int g  = lane >> 2, t4 = lane & 3;

    const int KT = KD / BK;

    // loader: per stage, 3 tiles x 512 16B-chunks; 6 cp.async per thread
    auto load_tiles = [&](int stage, int k0) {
        __half* sA  = smem + stage * STAGE_E;
        __half* sBh = sA + TILE_E;
        __half* sBl = sBh + TILE_E;
#pragma unroll
        for (int i = 0; i < 2; i++) {
            int c = i * 256 + tid;
            int r = c >> 2, c4 = c & 3;                 // row, 8-elem chunk in row
            cp16(sA + r * TS + c4 * 8, Ap + (size_t)(bm * BM + r) * KD + k0 + c4 * 8);
        }
#pragma unroll
        for (int i = 0; i < 2; i++) {
            int c = i * 256 + tid;
            int r = c >> 2, c4 = c & 3;
            size_t go = (size_t)(bn * BN + r) * KD + k0 + c4 * 8;
            cp16(sBh + r * TS + c4 * 8, Bh + go);
            cp16(sBl + r * TS + c4 * 8, Bl + go);
        }
    };

    load_tiles(0, 0);
    asm volatile("cp.async.commit_group;\n");

    float acc[2][8][4];
#pragma unroll
    for (int mi = 0; mi < 2; mi++)
#pragma unroll
        for (int ni = 0; ni < 8; ni++)
#pragma unroll
            for (int q = 0; q < 4; q++) acc[mi][ni][q] = 0.f;

    for (int kt = 0; kt < KT; ++kt) {
        if (kt + 1 < KT) {
            load_tiles((kt + 1) & 1, (kt + 1) * BK);
            asm volatile("cp.async.commit_group;\n");
            asm volatile("cp.async.wait_group 1;\n");
        } else {
            asm volatile("cp.async.wait_group 0;\n");
        }
        __syncthreads();

        const __half* sA  = smem + (kt & 1) * STAGE_E;
        const __half* sBh = sA + TILE_E;
        const __half* sBl = sBh + TILE_E;

#pragma unroll
        for (int ks = 0; ks < 2; ks++) {
            int k = ks * 16;
            uint32_t ah[2][4];
#pragma unroll
            for (int mi = 0; mi < 2; mi++) {
                int r0 = m0 + mi * 16 + g;
                ah[mi][0] = ld32(sA + (r0)     * TS + k + 2 * t4);
                ah[mi][1] = ld32(sA + (r0 + 8) * TS + k + 2 * t4);
                ah[mi][2] = ld32(sA + (r0)     * TS + k + 8 + 2 * t4);
                ah[mi][3] = ld32(sA + (r0 + 8) * TS + k + 8 + 2 * t4);
            }
#pragma unroll
            for (int ni = 0; ni < 8; ni++) {
                int c0 = n0 + ni * 8 + g;
                uint32_t bh[2], bl[2];
                bh[0] = ld32(sBh + (size_t)c0 * TS + k + 2 * t4);
                bh[1] = ld32(sBh + (size_t)c0 * TS + k + 8 + 2 * t4);
                bl[0] = ld32(sBl + (size_t)c0 * TS + k + 2 * t4);
                bl[1] = ld32(sBl + (size_t)c0 * TS + k + 8 + 2 * t4);
#pragma unroll
                for (int mi = 0; mi < 2; mi++) {
                    mma16(acc[mi][ni], ah[mi], bh);    // a_h * b_h
                    mma16(acc[mi][ni], ah[mi], bl);    // a_h * b_l
                }
            }
        }
        __syncthreads();
    }

    // epilogue
#pragma unroll
    for (int mi = 0; mi < 2; mi++) {
#pragma unroll
        for (int half_i = 0; half_i < 2; half_i++) {
            int r  = m0 + mi * 16 + half_i * 8 + g;
            int gm = bm * BM + r;
            if (gm < count) {
                if (EPI == 1) {
                    size_t rowoff = (size_t)gm * ND;
#pragma unroll
                    for (int ni = 0; ni < 8; ni++) {
                        int cc = bn * BN + n0 + ni * 8 + 2 * t4;
                        float2 bb = *(const float2*)(bias + cc);
                        float v0 = acc[mi][ni][half_i * 2 + 0] + bb.x;
                        float v1 = acc[mi][ni][half_i * 2 + 1] + bb.y;
                        v0 = v0 > 0.f ? v0 : 0.f;
                        v1 = v1 > 0.f ? v1 : 0.f;
                        *(__half2*)(g_C1 + rowoff + cc) = __floats2half2_rn(v0, v1);
                    }
                } else {
                    int orow = g_rows[gm];
                    size_t rowoff = (size_t)orow * ND;
#pragma unroll
                    for (int ni = 0; ni < 8; ni++) {
                        int cc = bn * BN + n0 + ni * 8 + 2 * t4;
                        float2 bb  = *(const float2*)(bias + cc);
                        float2* p  = (float2*)(g_base + rowoff + cc);
                        float2 old = *p;
                        old.x += acc[mi][ni][half_i * 2 + 0] + bb.x;
                        old.y += acc[mi][ni][half_i * 2 + 1] + bb.y;
                        *p = old;
                    }
                }
            }
        }
    }
}

// ---------------- K4: LayerNorm (warp per row) ----------------
__global__ void __launch_bounds__(256) ln_kernel(const float* __restrict__ gam,
                                                 const float* __restrict__ bet,
                                                 float* __restrict__ out)
{
    int widx = (blockIdx.x * blockDim.x + threadIdx.x) >> 5;
    int lane = threadIdx.x & 31;
    if (widx >= NT) return;

    const float4* src = (const float4*)(g_base + (size_t)widx * HID);
    float4 v[6];
    float s = 0.f, s2 = 0.f;
#pragma unroll
    for (int i = 0; i < 6; i++) {
        v[i] = src[lane + i * 32];
        s  += v[i].x + v[i].y + v[i].z + v[i].w;
        s2 += v[i].x * v[i].x + v[i].y * v[i].y + v[i].z * v[i].z + v[i].w * v[i].w;
    }
#pragma unroll
    for (int o = 16; o > 0; o >>= 1) {
        s  += __shfl_xor_sync(0xffffffffu, s,  o);
        s2 += __shfl_xor_sync(0xffffffffu, s2, o);
    }
    float mu  = s * (1.f / HID);
    float var = s2 * (1.f / HID) - mu * mu;
    float inv = rsqrtf(var + 1e-12f);

    const float4* gg = (const float4*)gam;
    const float4* bb = (const float4*)bet;
    float4* dst = (float4*)(out + (size_t)widx * HID);
#pragma unroll
    for (int i = 0; i < 6; i++) {
        int j = lane + i * 32;
        float4 G = gg[j], Bv = bb[j];
        float4 o;
        o.x = (v[i].x - mu) * inv * G.x + Bv.x;
        o.y = (v[i].y - mu) * inv * G.y + Bv.y;
        o.z = (v[i].z - mu) * inv * G.z + Bv.z;
        o.w = (v[i].w - mu) * inv * G.w + Bv.w;
        dst[j] = o;
    }
}

// ---------------- launch ----------------
extern "C" void kernel_launch(void* const* d_in, const int* in_sizes, int n_in,
                              void* d_out, int out_size)
{
    // Locate SMILES_fps by its unique size (B*S*FP_DIM = 25,165,824); any scalar
    // inputs (batch_size, max_batch_seq_len) precede it. Rest follow in order.
    int off = 0;
    for (int i = 0; i < n_in; i++)
        if (in_sizes[i] == NT * HID) { off = i; break; }

    const float* fps   = (const float*)d_in[off + 0];
    const int*   words = (const int*)  d_in[off + 1];
    const float* vals  = (const float*)d_in[off + 2];
    const int*   tts   = (const int*)  d_in[off + 3];
    const int*   poss  = (const int*)  d_in[off + 4];
    const float* fc1w  = (const float*)d_in[off + 5];
    const float* fc1b  = (const float*)d_in[off + 6];
    const float* fc2w  = (const float*)d_in[off + 7];
    const float* fc2b  = (const float*)d_in[off + 8];
    const float* prop  = (const float*)d_in[off + 9];
    const float* valw  = (const float*)d_in[off + 10];
    const float* valb  = (const float*)d_in[off + 11];
    const float* pose  = (const float*)d_in[off + 12];
    const float* typee = (const float*)d_in[off + 13];
    const float* lng   = (const float*)d_in[off + 14];
    const float* lnb   = (const float*)d_in[off + 15];
    float* out = (float*)d_out;

    const int smem_bytes = SMEM_E * 2;      // 61440
    cudaFuncSetAttribute(gemm_fp16x2<1>, cudaFuncAttributeMaxDynamicSharedMemorySize, smem_bytes);
    cudaFuncSetAttribute(gemm_fp16x2<2>, cudaFuncAttributeMaxDynamicSharedMemorySize, smem_bytes);

    zero_kernel<<<1, 1>>>();
    transpose_split<1><<<dim3(HID / 32, INTER / 32), dim3(32, 8)>>>(fc1w, HID, INTER);
    transpose_split<2><<<dim3(INTER / 32, HID / 32), dim3(32, 8)>>>(fc2w, INTER, HID);
    base_kernel<<<NT / 8, 256>>>(fps, words, vals, tts, poss, prop, valw, valb, pose, typee);
    gemm_fp16x2<1><<<dim3(INTER / BN, NT / BM), 256, smem_bytes>>>(fc1b);
    gemm_fp16x2<2><<<dim3(HID / BN, NT / BM), 256, smem_bytes>>>(fc2b);
    ln_kernel<<<NT / 8, 256>>>(lng, lnb, out);
}